// round 2
// baseline (speedup 1.0000x reference)
#include <cuda_runtime.h>
#include <math.h>

#define NN 100000
#define NE 3200000

// ---------------- scratch (device globals; no runtime allocation) ----------------
__device__ int   g_src[NE];
__device__ int   g_dst[NE];
__device__ float g_u[NE];

__device__ float g_y01[NN * 64];   // layer1: [y0(32) | y1(32)] per node
__device__ float g_r1 [NN * 32];
__device__ float g_agg1[NN * 32];
__device__ float g_cnt[NN];
__device__ float g_h  [NN * 32];

__device__ float g_z01[NN * 32];   // layer2: [z0(16) | z1(16)] per node
__device__ float g_r2 [NN * 16];
__device__ float g_agg2[NN * 16];

__device__ int g_is64;             // edge_index layout flag

// ---------------- detect int64 vs int32 edge_index layout ----------------
// If edge_index is int64 (values < 2^31), every odd 32-bit word of the first
// 64 pairs is zero. Under int32 layout with random indices the probability of
// that is ~(1e-5)^64 ~= 0.
__global__ void detect_kernel(const int* __restrict__ ei32) {
    if (blockIdx.x == 0 && threadIdx.x == 0) {
        int is64 = 1;
        for (int i = 0; i < 64; i++)
            if (ei32[2 * i + 1] != 0) { is64 = 0; break; }
        g_is64 = is64;
    }
}

// ---------------- edge preprocessing: decode indices, clip u ----------------
__global__ void prep_edges(const int* __restrict__ ei32,
                           const float* __restrict__ ea) {
    int e = blockIdx.x * blockDim.x + threadIdx.x;
    if (e >= NE) return;
    int s, d;
    if (g_is64) {
        s = ei32[2 * e];                 // low word of int64
        d = ei32[2 * (NE + e)];
    } else {
        s = ei32[e];
        d = ei32[NE + e];
    }
    // defensive clamp: wrong values -> wrong answer (rel_err), never a crash
    s = min(max(s, 0), NN - 1);
    d = min(max(d, 0), NN - 1);
    g_src[e] = s;
    g_dst[e] = d;
    g_u[e]   = fminf(fmaxf(ea[e], 0.0f), 1.0f);
}

// ---------------- zero accumulators ----------------
__global__ void zero_kernel() {
    int t = blockIdx.x * blockDim.x + threadIdx.x;
    if (t < NN * 32)            g_agg1[t] = 0.0f;
    else if (t < NN * 33)       g_cnt[t - NN * 32] = 0.0f;
    else if (t < NN * 49)       g_agg2[t - NN * 33] = 0.0f;
}

// ---------------- fused per-node GEMM: xin[N,32] @ [W0|W1|root] ----------------
template<int LAYER>
__global__ __launch_bounds__(128) void gemm_kernel(
    const float* __restrict__ xin_arg,
    const float* __restrict__ W,      // [2,32,FO]
    const float* __restrict__ root)   // [32,FO]
{
    constexpr int FO = (LAYER == 1) ? 32 : 16;
    constexpr int NC = 3 * FO;
    const float* xin  = (LAYER == 1) ? xin_arg : g_h;
    float*       pack = (LAYER == 1) ? g_y01 : g_z01;
    float*       rout = (LAYER == 1) ? g_r1  : g_r2;

    __shared__ __align__(16) float sx[256 * 33];
    __shared__ __align__(16) float sW[32 * NC];

    int tid  = threadIdx.x;
    int base = blockIdx.x * 256;

    for (int idx = tid; idx < 32 * NC; idx += 128) {
        int k = idx / NC, j = idx % NC;
        float v;
        if (j < FO)            v = W[k * FO + j];
        else if (j < 2 * FO)   v = W[(32 + k) * FO + (j - FO)];
        else                   v = root[k * FO + (j - 2 * FO)];
        sW[idx] = v;
    }
    for (int idx = tid; idx < 256 * 32; idx += 128) {
        int nl = idx >> 5, k = idx & 31;
        int n = base + nl;
        sx[nl * 33 + k] = (n < NN) ? xin[(size_t)n * 32 + k] : 0.0f;
    }
    __syncthreads();

    int n0 = base + 2 * tid, n1 = n0 + 1;
    float xr0[32], xr1[32];
#pragma unroll
    for (int k = 0; k < 32; k++) {
        xr0[k] = sx[(2 * tid) * 33 + k];
        xr1[k] = sx[(2 * tid + 1) * 33 + k];
    }

    for (int jg = 0; jg < NC / 4; jg++) {
        float4 a0 = make_float4(0.f, 0.f, 0.f, 0.f);
        float4 a1 = make_float4(0.f, 0.f, 0.f, 0.f);
#pragma unroll
        for (int k = 0; k < 32; k++) {
            float4 w = *reinterpret_cast<const float4*>(&sW[k * NC + jg * 4]);
            a0.x += xr0[k] * w.x; a0.y += xr0[k] * w.y;
            a0.z += xr0[k] * w.z; a0.w += xr0[k] * w.w;
            a1.x += xr1[k] * w.x; a1.y += xr1[k] * w.y;
            a1.z += xr1[k] * w.z; a1.w += xr1[k] * w.w;
        }
        int j = jg * 4;
        if (j < 2 * FO) {
            if (n0 < NN) *reinterpret_cast<float4*>(&pack[(size_t)n0 * 2 * FO + j]) = a0;
            if (n1 < NN) *reinterpret_cast<float4*>(&pack[(size_t)n1 * 2 * FO + j]) = a1;
        } else {
            int jj = j - 2 * FO;
            if (n0 < NN) *reinterpret_cast<float4*>(&rout[(size_t)n0 * FO + jj]) = a0;
            if (n1 < NN) *reinterpret_cast<float4*>(&rout[(size_t)n1 * FO + jj]) = a1;
        }
    }
}

// ---------------- edge scatter: lerp(y0,y1,u) atomically into agg[dst] ----------------
template<int LAYER>
__global__ void edge_kernel() {
    constexpr int FO  = (LAYER == 1) ? 32 : 16;
    constexpr int LPE = FO / 4;                       // lanes per edge (float4 each)
    const float* buf = (LAYER == 1) ? g_y01 : g_z01;
    float*       agg = (LAYER == 1) ? g_agg1 : g_agg2;

    int t = blockIdx.x * blockDim.x + threadIdx.x;
    int e = t / LPE;
    if (e >= NE) return;
    int l = t - e * LPE;

    int src = g_src[e];
    int dst = g_dst[e];
    float u = g_u[e];

    const float4* a = reinterpret_cast<const float4*>(buf + (size_t)src * (2 * FO));
    float4 v0 = a[l];
    float4 v1 = a[LPE + l];
    float4 m;
    m.x = v0.x + u * (v1.x - v0.x);
    m.y = v0.y + u * (v1.y - v0.y);
    m.z = v0.z + u * (v1.z - v0.z);
    m.w = v0.w + u * (v1.w - v0.w);

    float* p = agg + (size_t)dst * FO + l * 4;
    asm volatile("red.global.add.v4.f32 [%0], {%1,%2,%3,%4};"
                 :: "l"(p), "f"(m.x), "f"(m.y), "f"(m.z), "f"(m.w) : "memory");
    if (LAYER == 1 && l == 0) {
        float* c = g_cnt + dst;
        asm volatile("red.global.add.f32 [%0], %1;" :: "l"(c), "f"(1.0f) : "memory");
    }
}

// ---------------- node pass 1: h = relu(agg1/max(cnt,1) + r1 + b1) ----------------
__global__ void node1_kernel(const float* __restrict__ b1) {
    int t = blockIdx.x * blockDim.x + threadIdx.x;
    if (t >= NN * 8) return;
    int n = t >> 3, f = t & 7;
    float inv = 1.0f / fmaxf(g_cnt[n], 1.0f);
    float4 a = *reinterpret_cast<const float4*>(&g_agg1[(size_t)n * 32 + f * 4]);
    float4 r = *reinterpret_cast<const float4*>(&g_r1 [(size_t)n * 32 + f * 4]);
    float4 b = *reinterpret_cast<const float4*>(&b1[f * 4]);
    float4 o;
    o.x = fmaxf(a.x * inv + r.x + b.x, 0.0f);
    o.y = fmaxf(a.y * inv + r.y + b.y, 0.0f);
    o.z = fmaxf(a.z * inv + r.z + b.z, 0.0f);
    o.w = fmaxf(a.w * inv + r.w + b.w, 0.0f);
    *reinterpret_cast<float4*>(&g_h[(size_t)n * 32 + f * 4]) = o;
}

// ---------------- node pass 2: log_softmax(agg2/cnt + r2 + b2) ----------------
__global__ void node2_kernel(const float* __restrict__ b2,
                             float* __restrict__ out) {
    int n = blockIdx.x * blockDim.x + threadIdx.x;
    if (n >= NN) return;
    float inv = 1.0f / fmaxf(g_cnt[n], 1.0f);
    float v[16];
#pragma unroll
    for (int j = 0; j < 16; j++)
        v[j] = g_agg2[(size_t)n * 16 + j] * inv + g_r2[(size_t)n * 16 + j] + b2[j];
    float m = v[0];
#pragma unroll
    for (int j = 1; j < 16; j++) m = fmaxf(m, v[j]);
    float s = 0.0f;
#pragma unroll
    for (int j = 0; j < 16; j++) s += expf(v[j] - m);
    float lo = logf(s);
#pragma unroll
    for (int j = 0; j < 16; j++)
        out[(size_t)n * 16 + j] = v[j] - m - lo;
}

// ---------------- launch ----------------
extern "C" void kernel_launch(void* const* d_in, const int* in_sizes, int n_in,
                              void* d_out, int out_size) {
    const float* x   = (const float*)d_in[0];
    const int*   ei  = (const int*)d_in[1];   // int32 OR int64 (detected on device)
    const float* ea  = (const float*)d_in[2];
    const float* W1  = (const float*)d_in[3];
    const float* r1w = (const float*)d_in[4];
    const float* b1  = (const float*)d_in[5];
    const float* W2  = (const float*)d_in[6];
    const float* r2w = (const float*)d_in[7];
    const float* b2  = (const float*)d_in[8];
    float* out = (float*)d_out;

    detect_kernel<<<1, 32>>>(ei);
    prep_edges<<<(NE + 255) / 256, 256>>>(ei, ea);
    zero_kernel<<<(NN * 49 + 255) / 256, 256>>>();

    gemm_kernel<1><<<(NN + 255) / 256, 128>>>(x, W1, r1w);
    edge_kernel<1><<<(NE * 8) / 256, 256>>>();              // 8 lanes/edge
    node1_kernel<<<(NN * 8 + 255) / 256, 256>>>(b1);

    gemm_kernel<2><<<(NN + 255) / 256, 128>>>(nullptr, W2, r2w);
    edge_kernel<2><<<(NE * 4) / 256, 256>>>();              // 4 lanes/edge
    node2_kernel<<<(NN + 255) / 256, 256>>>(b2, out);
}

// round 3
// speedup vs baseline: 1.1023x; 1.1023x over previous
#include <cuda_runtime.h>
#include <cuda_fp16.h>
#include <math.h>

#define NN 100000
#define NE 3200000

// ---------------- scratch (device globals; no runtime allocation) ----------------
__device__ int     g_src[NE];
__device__ int     g_dst[NE];
__device__ float   g_u[NE];

__device__ __half2 g_y01h[NN * 32];   // layer1: half2(y0[f], y1[f]) per node, 32 feats
__device__ float   g_r1 [NN * 32];
__device__ float   g_agg1[NN * 32];
__device__ float   g_cnt[NN];
__device__ float   g_h  [NN * 32];

__device__ __half2 g_z01h[NN * 16];   // layer2: half2(z0[f], z1[f]) per node, 16 feats
__device__ float   g_r2 [NN * 16];
__device__ float   g_agg2[NN * 16];

__device__ int g_is64;                // edge_index layout flag

// ---------------- detect int64 vs int32 edge_index layout ----------------
__global__ void detect_kernel(const int* __restrict__ ei32) {
    if (blockIdx.x == 0 && threadIdx.x == 0) {
        int is64 = 1;
        for (int i = 0; i < 64; i++)
            if (ei32[2 * i + 1] != 0) { is64 = 0; break; }
        g_is64 = is64;
    }
}

// ---------------- zero accumulators (must run before prep: prep adds counts) ----
__global__ void zero_kernel() {
    int t = blockIdx.x * blockDim.x + threadIdx.x;
    if (t < NN * 32)            g_agg1[t] = 0.0f;
    else if (t < NN * 33)       g_cnt[t - NN * 32] = 0.0f;
    else if (t < NN * 49)       g_agg2[t - NN * 33] = 0.0f;
}

// ---------------- edge prep: decode indices, clip u, accumulate counts ----------
__global__ void prep_edges(const int* __restrict__ ei32,
                           const float* __restrict__ ea) {
    int e = blockIdx.x * blockDim.x + threadIdx.x;
    if (e >= NE) return;
    int s, d;
    if (g_is64) {
        s = ei32[2 * e];
        d = ei32[2 * (NE + e)];
    } else {
        s = ei32[e];
        d = ei32[NE + e];
    }
    s = min(max(s, 0), NN - 1);
    d = min(max(d, 0), NN - 1);
    g_src[e] = s;
    g_dst[e] = d;
    g_u[e]   = fminf(fmaxf(ea[e], 0.0f), 1.0f);
    float* c = g_cnt + d;
    asm volatile("red.global.add.f32 [%0], %1;" :: "l"(c), "f"(1.0f) : "memory");
}

// ---------------- per-node GEMM: xin[N,32] @ [W0|W1|root] ----------------
// Writes pack[n][f] = half2(y0[f], y1[f])  and  rout[n][f] = x@root (fp32).
template<int LAYER>
__global__ __launch_bounds__(128) void gemm_kernel(
    const float* __restrict__ xin_arg,
    const float* __restrict__ W,      // [2,32,FO]
    const float* __restrict__ root)   // [32,FO]
{
    constexpr int FO = (LAYER == 1) ? 32 : 16;
    const float* xin  = (LAYER == 1) ? xin_arg : g_h;
    __half2*     pack = (LAYER == 1) ? g_y01h : g_z01h;
    float*       rout = (LAYER == 1) ? g_r1  : g_r2;

    __shared__ __align__(16) float sW0[32 * FO];
    __shared__ __align__(16) float sW1[32 * FO];
    __shared__ __align__(16) float sR [32 * FO];

    int tid  = threadIdx.x;
    int base = blockIdx.x * 256;

    for (int i = tid; i < 32 * FO; i += 128) {
        sW0[i] = W[i];
        sW1[i] = W[32 * FO + i];
        sR [i] = root[i];
    }

    int n0 = base + 2 * tid, n1 = n0 + 1;
    float xr0[32], xr1[32];
#pragma unroll
    for (int q = 0; q < 8; q++) {
        float4 v0 = make_float4(0.f,0.f,0.f,0.f), v1 = v0;
        if (n0 < NN) v0 = *reinterpret_cast<const float4*>(&xin[(size_t)n0 * 32 + q * 4]);
        if (n1 < NN) v1 = *reinterpret_cast<const float4*>(&xin[(size_t)n1 * 32 + q * 4]);
        xr0[q*4+0]=v0.x; xr0[q*4+1]=v0.y; xr0[q*4+2]=v0.z; xr0[q*4+3]=v0.w;
        xr1[q*4+0]=v1.x; xr1[q*4+1]=v1.y; xr1[q*4+2]=v1.z; xr1[q*4+3]=v1.w;
    }
    __syncthreads();

    // basis strips: y0,y1 for both nodes, 4 output cols at a time
    for (int jg = 0; jg < FO / 4; jg++) {
        float4 a0y0 = make_float4(0.f,0.f,0.f,0.f), a0y1 = a0y0;
        float4 a1y0 = a0y0, a1y1 = a0y0;
#pragma unroll
        for (int k = 0; k < 32; k++) {
            float4 w0 = *reinterpret_cast<const float4*>(&sW0[k * FO + jg * 4]);
            float4 w1 = *reinterpret_cast<const float4*>(&sW1[k * FO + jg * 4]);
            float x0 = xr0[k], x1 = xr1[k];
            a0y0.x += x0*w0.x; a0y0.y += x0*w0.y; a0y0.z += x0*w0.z; a0y0.w += x0*w0.w;
            a0y1.x += x0*w1.x; a0y1.y += x0*w1.y; a0y1.z += x0*w1.z; a0y1.w += x0*w1.w;
            a1y0.x += x1*w0.x; a1y0.y += x1*w0.y; a1y0.z += x1*w0.z; a1y0.w += x1*w0.w;
            a1y1.x += x1*w1.x; a1y1.y += x1*w1.y; a1y1.z += x1*w1.z; a1y1.w += x1*w1.w;
        }
        __half2 h0[4], h1[4];
        h0[0] = __floats2half2_rn(a0y0.x, a0y1.x);
        h0[1] = __floats2half2_rn(a0y0.y, a0y1.y);
        h0[2] = __floats2half2_rn(a0y0.z, a0y1.z);
        h0[3] = __floats2half2_rn(a0y0.w, a0y1.w);
        h1[0] = __floats2half2_rn(a1y0.x, a1y1.x);
        h1[1] = __floats2half2_rn(a1y0.y, a1y1.y);
        h1[2] = __floats2half2_rn(a1y0.z, a1y1.z);
        h1[3] = __floats2half2_rn(a1y0.w, a1y1.w);
        if (n0 < NN) *reinterpret_cast<float4*>(&pack[(size_t)n0 * FO + jg * 4]) =
            *reinterpret_cast<float4*>(h0);
        if (n1 < NN) *reinterpret_cast<float4*>(&pack[(size_t)n1 * FO + jg * 4]) =
            *reinterpret_cast<float4*>(h1);
    }

    // root strips (fp32)
    for (int jg = 0; jg < FO / 4; jg++) {
        float4 r0 = make_float4(0.f,0.f,0.f,0.f), r1 = r0;
#pragma unroll
        for (int k = 0; k < 32; k++) {
            float4 w = *reinterpret_cast<const float4*>(&sR[k * FO + jg * 4]);
            float x0 = xr0[k], x1 = xr1[k];
            r0.x += x0*w.x; r0.y += x0*w.y; r0.z += x0*w.z; r0.w += x0*w.w;
            r1.x += x1*w.x; r1.y += x1*w.y; r1.z += x1*w.z; r1.w += x1*w.w;
        }
        if (n0 < NN) *reinterpret_cast<float4*>(&rout[(size_t)n0 * FO + jg * 4]) = r0;
        if (n1 < NN) *reinterpret_cast<float4*>(&rout[(size_t)n1 * FO + jg * 4]) = r1;
    }
}

// ---------------- edge scatter: lerp(y0,y1,u) atomically into agg[dst] ----------------
// LPE lanes per edge; each lane gathers 4 half2 pairs (16B) and emits one red.v4.
template<int LAYER>
__global__ void edge_kernel() {
    constexpr int FO  = (LAYER == 1) ? 32 : 16;
    constexpr int LPE = FO / 4;
    const __half2* buf = (LAYER == 1) ? g_y01h : g_z01h;
    float*         agg = (LAYER == 1) ? g_agg1 : g_agg2;

    int t = blockIdx.x * blockDim.x + threadIdx.x;   // grid sized exactly
    int e = t / LPE;
    int l = t - e * LPE;
    int lane = threadIdx.x & 31;
    int leader = lane & ~(LPE - 1);

    int s = 0, d = 0; float u = 0.f;
    if ((lane & (LPE - 1)) == 0) {
        s = g_src[e];
        d = g_dst[e];
        u = g_u[e];
    }
    s = __shfl_sync(0xffffffffu, s, leader);
    d = __shfl_sync(0xffffffffu, d, leader);
    u = __shfl_sync(0xffffffffu, u, leader);

    float4 raw = *reinterpret_cast<const float4*>(buf + (size_t)s * FO + l * 4);
    const __half2* hp = reinterpret_cast<const __half2*>(&raw);
    float4 m;
    {
        float2 p0 = __half22float2(hp[0]);
        float2 p1 = __half22float2(hp[1]);
        float2 p2 = __half22float2(hp[2]);
        float2 p3 = __half22float2(hp[3]);
        m.x = p0.x + u * (p0.y - p0.x);
        m.y = p1.x + u * (p1.y - p1.x);
        m.z = p2.x + u * (p2.y - p2.x);
        m.w = p3.x + u * (p3.y - p3.x);
    }
    float* p = agg + (size_t)d * FO + l * 4;
    asm volatile("red.global.add.v4.f32 [%0], {%1,%2,%3,%4};"
                 :: "l"(p), "f"(m.x), "f"(m.y), "f"(m.z), "f"(m.w) : "memory");
}

// ---------------- node pass 1: h = relu(agg1/max(cnt,1) + r1 + b1) ----------------
__global__ void node1_kernel(const float* __restrict__ b1) {
    int t = blockIdx.x * blockDim.x + threadIdx.x;
    if (t >= NN * 8) return;
    int n = t >> 3, f = t & 7;
    float inv = 1.0f / fmaxf(g_cnt[n], 1.0f);
    float4 a = *reinterpret_cast<const float4*>(&g_agg1[(size_t)n * 32 + f * 4]);
    float4 r = *reinterpret_cast<const float4*>(&g_r1 [(size_t)n * 32 + f * 4]);
    float4 b = *reinterpret_cast<const float4*>(&b1[f * 4]);
    float4 o;
    o.x = fmaxf(a.x * inv + r.x + b.x, 0.0f);
    o.y = fmaxf(a.y * inv + r.y + b.y, 0.0f);
    o.z = fmaxf(a.z * inv + r.z + b.z, 0.0f);
    o.w = fmaxf(a.w * inv + r.w + b.w, 0.0f);
    *reinterpret_cast<float4*>(&g_h[(size_t)n * 32 + f * 4]) = o;
}

// ---------------- node pass 2: log_softmax(agg2/cnt + r2 + b2) ----------------
__global__ void node2_kernel(const float* __restrict__ b2,
                             float* __restrict__ out) {
    int n = blockIdx.x * blockDim.x + threadIdx.x;
    if (n >= NN) return;
    float inv = 1.0f / fmaxf(g_cnt[n], 1.0f);
    float v[16];
#pragma unroll
    for (int j = 0; j < 16; j++)
        v[j] = g_agg2[(size_t)n * 16 + j] * inv + g_r2[(size_t)n * 16 + j] + b2[j];
    float m = v[0];
#pragma unroll
    for (int j = 1; j < 16; j++) m = fmaxf(m, v[j]);
    float s = 0.0f;
#pragma unroll
    for (int j = 0; j < 16; j++) s += expf(v[j] - m);
    float lo = logf(s);
#pragma unroll
    for (int j = 0; j < 16; j++)
        out[(size_t)n * 16 + j] = v[j] - m - lo;
}

// ---------------- launch ----------------
extern "C" void kernel_launch(void* const* d_in, const int* in_sizes, int n_in,
                              void* d_out, int out_size) {
    const float* x   = (const float*)d_in[0];
    const int*   ei  = (const int*)d_in[1];
    const float* ea  = (const float*)d_in[2];
    const float* W1  = (const float*)d_in[3];
    const float* r1w = (const float*)d_in[4];
    const float* b1  = (const float*)d_in[5];
    const float* W2  = (const float*)d_in[6];
    const float* r2w = (const float*)d_in[7];
    const float* b2  = (const float*)d_in[8];
    float* out = (float*)d_out;

    detect_kernel<<<1, 32>>>(ei);
    zero_kernel<<<(NN * 49 + 255) / 256, 256>>>();
    prep_edges<<<(NE + 255) / 256, 256>>>(ei, ea);

    gemm_kernel<1><<<(NN + 255) / 256, 128>>>(x, W1, r1w);
    edge_kernel<1><<<(NE * 8) / 256, 256>>>();              // 8 lanes/edge
    node1_kernel<<<(NN * 8 + 255) / 256, 256>>>(b1);

    gemm_kernel<2><<<(NN + 255) / 256, 128>>>(nullptr, W2, r2w);
    edge_kernel<2><<<(NE * 4) / 256, 256>>>();              // 4 lanes/edge
    node2_kernel<<<(NN + 255) / 256, 256>>>(b2, out);
}